// round 13
// baseline (speedup 1.0000x reference)
#include <cuda_runtime.h>
#include <cuda_bf16.h>
#include <cstdint>
#include <math.h>

#define BB 16
#define TT 1024
#define DD 1024
#define HH 16
#define HDD 64

// ---------------------------------------------------------------------------
// Scratch (allocation-free rule: __device__ globals)
// ---------------------------------------------------------------------------
__device__ __nv_bfloat16 g_xh[BB * TT * DD];        // X hi
__device__ __nv_bfloat16 g_xl[BB * TT * DD];        // X lo
__device__ __nv_bfloat16 g_wqkvT_h[3 * DD * DD];    // WqkvT [3D][D] hi
__device__ __nv_bfloat16 g_wqkvT_l[3 * DD * DD];
__device__ __nv_bfloat16 g_woutT_h[DD * DD];        // WoutT [D][D] hi
__device__ __nv_bfloat16 g_woutT_l[DD * DD];
__device__ __nv_bfloat16 g_qkvH[BB * TT * 3 * DD];  // qkv hi (Q pre-scaled)
__device__ __nv_bfloat16 g_qkvL[BB * TT * 3 * DD];  // qkv lo
__device__ __nv_bfloat16 g_attnH[BB * TT * DD];     // attention out hi
__device__ __nv_bfloat16 g_attnL[BB * TT * DD];     // attention out lo

// ---------------------------------------------------------------------------
// helpers
// ---------------------------------------------------------------------------
__device__ __forceinline__ unsigned ssa(const void* p) {
    return (unsigned)__cvta_generic_to_shared(p);
}
__device__ __forceinline__ void bf16split(float x, __nv_bfloat16& hi, __nv_bfloat16& lo) {
    hi = __float2bfloat16(x);
    lo = __float2bfloat16(x - __bfloat162float(hi));
}
__device__ __forceinline__ unsigned pack2(__nv_bfloat16 a, __nv_bfloat16 b) {
    __nv_bfloat162 v(a, b);
    return *reinterpret_cast<unsigned*>(&v);
}
__device__ __forceinline__ void ldsm4(unsigned& r0, unsigned& r1,
                                      unsigned& r2, unsigned& r3, unsigned a) {
    asm volatile("ldmatrix.sync.aligned.m8n8.x4.shared.b16 {%0,%1,%2,%3}, [%4];"
                 : "=r"(r0), "=r"(r1), "=r"(r2), "=r"(r3) : "r"(a));
}
__device__ __forceinline__ void ldsm4t(unsigned& r0, unsigned& r1,
                                       unsigned& r2, unsigned& r3, unsigned a) {
    asm volatile("ldmatrix.sync.aligned.m8n8.x4.trans.shared.b16 {%0,%1,%2,%3}, [%4];"
                 : "=r"(r0), "=r"(r1), "=r"(r2), "=r"(r3) : "r"(a));
}
__device__ __forceinline__ void mma16(float* c,
                                      unsigned a0, unsigned a1, unsigned a2, unsigned a3,
                                      unsigned b0, unsigned b1) {
    asm volatile(
        "mma.sync.aligned.m16n8k16.row.col.f32.bf16.bf16.f32 "
        "{%0,%1,%2,%3}, {%4,%5,%6,%7}, {%8,%9}, {%0,%1,%2,%3};"
        : "+f"(c[0]), "+f"(c[1]), "+f"(c[2]), "+f"(c[3])
        : "r"(a0), "r"(a1), "r"(a2), "r"(a3), "r"(b0), "r"(b1));
}
__device__ __forceinline__ void cpa16(uint32_t s, const void* g) {
    asm volatile("cp.async.cg.shared.global [%0], [%1], 16;" :: "r"(s), "l"(g));
}
#define CP_COMMIT() asm volatile("cp.async.commit_group;" ::: "memory")
#define CP_WAIT(n)  asm volatile("cp.async.wait_group %0;" :: "n"(n) : "memory")

#define SW128(off) ((off) ^ (((off) >> 3) & 0x70))
#define SW64B(off) ((off) ^ (((off) >> 3) & 0x30))

// ---------------------------------------------------------------------------
// Pre-pass 1: split fp32 -> bf16 hi/lo
// ---------------------------------------------------------------------------
__global__ void split_kernel(const float* __restrict__ X,
                             __nv_bfloat16* __restrict__ H,
                             __nv_bfloat16* __restrict__ L, int n4)
{
    int i = blockIdx.x * blockDim.x + threadIdx.x;
    if (i >= n4) return;
    float4 v = reinterpret_cast<const float4*>(X)[i];
    float f[4] = {v.x, v.y, v.z, v.w};
    __nv_bfloat16 h[4], l[4];
    #pragma unroll
    for (int j = 0; j < 4; j++) bf16split(f[j], h[j], l[j]);
    reinterpret_cast<uint2*>(H)[i] = make_uint2(pack2(h[0], h[1]), pack2(h[2], h[3]));
    reinterpret_cast<uint2*>(L)[i] = make_uint2(pack2(l[0], l[1]), pack2(l[2], l[3]));
}

// ---------------------------------------------------------------------------
// Pre-pass 2: W [K][N] fp32 -> WT [N][K] bf16 hi/lo
// ---------------------------------------------------------------------------
__global__ void transpose_split_kernel(const float* __restrict__ W,
                                       __nv_bfloat16* __restrict__ Th,
                                       __nv_bfloat16* __restrict__ Tl,
                                       int K, int N)
{
    __shared__ float t[32][33];
    int n0 = blockIdx.x * 32, k0 = blockIdx.y * 32;
    int tx = threadIdx.x, ty = threadIdx.y;
    #pragma unroll
    for (int i = 0; i < 32; i += 8)
        t[ty + i][tx] = W[(size_t)(k0 + ty + i) * N + n0 + tx];
    __syncthreads();
    #pragma unroll
    for (int i = 0; i < 32; i += 8) {
        float v = t[tx][ty + i];
        __nv_bfloat16 h, l;
        bf16split(v, h, l);
        Th[(size_t)(n0 + ty + i) * K + k0 + tx] = h;
        Tl[(size_t)(n0 + ty + i) * K + k0 + tx] = l;
    }
}

// ---------------------------------------------------------------------------
// bf16x2-split mma.sync GEMM, 3-stage cp.async pipeline, SW64-swizzled tiles.
// (unchanged from round-12 passing version)
// ---------------------------------------------------------------------------
__global__ void __launch_bounds__(256, 2)
gemm_mma_kernel(const __nv_bfloat16* __restrict__ Ah,
                const __nv_bfloat16* __restrict__ Al,
                const __nv_bfloat16* __restrict__ Bh,
                const __nv_bfloat16* __restrict__ Bl,
                const float* __restrict__ bias,
                float* __restrict__ Cf,
                __nv_bfloat16* __restrict__ Ch,
                __nv_bfloat16* __restrict__ Cl,
                int N, int K, int mode)
{
    extern __shared__ char dsm[];
    constexpr int STAGE = 32768;          // 4 arrays * 8192 B
    const uint32_t sb0 = ssa(dsm);

    const int tid = threadIdx.x;
    const int wid = tid >> 5;
    const int wr = wid & 3;
    const int wc = wid >> 2;
    const int lane = tid & 31;
    const int g = lane >> 2;
    const int t = lane & 3;
    const int lr  = lane & 7;
    const int tlo = (lane >> 3) & 1;
    const int thi = lane >> 4;
    const int blockRow = blockIdx.y * 128;
    const int blockCol = blockIdx.x * 128;
    const int NC = K / 32;                // 32 chunks

    float c[2][8][4];
    #pragma unroll
    for (int mf = 0; mf < 2; mf++)
        #pragma unroll
        for (int nf = 0; nf < 8; nf++)
            #pragma unroll
            for (int i = 0; i < 4; i++) c[mf][nf][i] = 0.f;

    auto load_chunk = [&](int cc) {
        const uint32_t sb = sb0 + (cc % 3) * STAGE;
        const int kt = cc * 32;
        #pragma unroll
        for (int i = 0; i < 2; i++) {
            int id = tid + i * 256;           // 0..511
            int row = id >> 2, u = id & 3;    // 128 rows x 4 x 16B
            uint32_t off = SW64B(row * 64 + u * 16);
            size_t ga = (size_t)(blockRow + row) * K + kt + u * 8;
            size_t gb = (size_t)(blockCol + row) * K + kt + u * 8;
            cpa16(sb + off,         Ah + ga);
            cpa16(sb +  8192 + off, Al + ga);
            cpa16(sb + 16384 + off, Bh + gb);
            cpa16(sb + 24576 + off, Bl + gb);
        }
        CP_COMMIT();
    };

    load_chunk(0);
    load_chunk(1);
    load_chunk(2);

    for (int cc = 0; cc < NC; cc++) {
        if (cc + 2 < NC)      CP_WAIT(2);
        else if (cc + 1 < NC) CP_WAIT(1);
        else                  CP_WAIT(0);
        __syncthreads();

        const uint32_t sb = sb0 + (cc % 3) * STAGE;
        #pragma unroll
        for (int ks = 0; ks < 2; ks++) {
            unsigned ah[2][4], al_[2][4];
            #pragma unroll
            for (int mf = 0; mf < 2; mf++) {
                int row = wr * 32 + mf * 16 + tlo * 8 + lr;
                uint32_t off = SW64B(row * 64 + ks * 32 + thi * 16);
                ldsm4(ah[mf][0], ah[mf][1], ah[mf][2], ah[mf][3], sb + off);
                ldsm4(al_[mf][0], al_[mf][1], al_[mf][2], al_[mf][3], sb + 8192 + off);
            }
            #pragma unroll
            for (int np = 0; np < 4; np++) {
                int nrow = wc * 64 + np * 16 + thi * 8 + lr;
                uint32_t off = SW64B(nrow * 64 + ks * 32 + tlo * 16);
                unsigned bh[4], bl[4];
                ldsm4(bh[0], bh[1], bh[2], bh[3], sb + 16384 + off);
                ldsm4(bl[0], bl[1], bl[2], bl[3], sb + 24576 + off);
                #pragma unroll
                for (int half = 0; half < 2; half++) {
                    int nf = np * 2 + half;
                    unsigned b0h = bh[2 * half], b1h = bh[2 * half + 1];
                    unsigned b0l = bl[2 * half], b1l = bl[2 * half + 1];
                    #pragma unroll
                    for (int mf = 0; mf < 2; mf++) {
                        mma16(c[mf][nf], ah[mf][0], ah[mf][1], ah[mf][2], ah[mf][3], b0h, b1h);
                        mma16(c[mf][nf], ah[mf][0], ah[mf][1], ah[mf][2], ah[mf][3], b0l, b1l);
                        mma16(c[mf][nf], al_[mf][0], al_[mf][1], al_[mf][2], al_[mf][3], b0h, b1h);
                    }
                }
            }
        }
        __syncthreads();
        if (cc + 3 < NC) load_chunk(cc + 3);
    }

    // epilogue
    const float qs = (mode == 1 && blockCol < DD) ? 0.125f : 1.0f;
    #pragma unroll
    for (int mf = 0; mf < 2; mf++) {
        int row = blockRow + wr * 32 + mf * 16 + g;
        #pragma unroll
        for (int nf = 0; nf < 8; nf++) {
            int col = blockCol + wc * 64 + nf * 8 + 2 * t;
            float bx = bias[col], by = bias[col + 1];
            float v0 = (c[mf][nf][0] + bx) * qs;
            float v1 = (c[mf][nf][1] + by) * qs;
            float v2 = (c[mf][nf][2] + bx) * qs;
            float v3 = (c[mf][nf][3] + by) * qs;
            if (mode == 0) {
                *reinterpret_cast<float2*>(&Cf[(size_t)row * N + col]) = make_float2(v0, v1);
                *reinterpret_cast<float2*>(&Cf[(size_t)(row + 8) * N + col]) = make_float2(v2, v3);
            } else {
                __nv_bfloat16 h0, l0, h1, l1;
                bf16split(v0, h0, l0); bf16split(v1, h1, l1);
                *reinterpret_cast<unsigned*>(&Ch[(size_t)row * N + col]) = pack2(h0, h1);
                *reinterpret_cast<unsigned*>(&Cl[(size_t)row * N + col]) = pack2(l0, l1);
                bf16split(v2, h0, l0); bf16split(v3, h1, l1);
                *reinterpret_cast<unsigned*>(&Ch[(size_t)(row + 8) * N + col]) = pack2(h0, h1);
                *reinterpret_cast<unsigned*>(&Cl[(size_t)(row + 8) * N + col]) = pack2(l0, l1);
            }
        }
    }
}

// ---------------------------------------------------------------------------
// Flash attention, bf16 3-term split, 128-row Q tiles.
// Block = 128 q rows of one (b,h); 256 threads = 8 warps; warp w owns rows
// 16w..16w+15. K/V tiles 64 keys, split commit groups (K and V separate):
// wait K -> S -> sync -> issue K(kt+1) -> softmax -> wait V -> PV -> issue V(kt+1).
// Smem: QH/QL 16 KB each + KH/KL/VH/VL 8 KB each = 64 KB; 2 CTAs/SM (reg-capped).
// ---------------------------------------------------------------------------
__global__ void __launch_bounds__(256, 2)
attn_tc_kernel(const __nv_bfloat16* __restrict__ qh,
               const __nv_bfloat16* __restrict__ ql,
               __nv_bfloat16* __restrict__ outH,
               __nv_bfloat16* __restrict__ outL)
{
    extern __shared__ char asm_[];
    const uint32_t QHs = ssa(asm_);
    const uint32_t QLs = QHs + 16384;
    const uint32_t KHs = QHs + 32768;
    const uint32_t KLs = QHs + 40960;
    const uint32_t VHs = QHs + 49152;
    const uint32_t VLs = QHs + 57344;

    const int b = blockIdx.z;
    const int h = blockIdx.y;
    const int qt = blockIdx.x;
    const int tid = threadIdx.x;
    const int w = tid >> 5;              // 0..7
    const int lane = tid & 31;
    const int g = lane >> 2;
    const int t = lane & 3;
    const int lr  = lane & 7;
    const int tlo = (lane >> 3) & 1;
    const int thi = lane >> 4;
    const int t0 = qt * 128;
    const int NT = TT / 64;

    const size_t rowstride = 3 * DD;
    const size_t base = (size_t)(b * TT) * rowstride + h * HDD;

    auto load_k = [&](int kt) {
        #pragma unroll
        for (int i = 0; i < 2; i++) {
            int id = tid + i * 256;                 // 0..511
            int r = id >> 3, u = id & 7;
            uint32_t so = SW128(r * 128 + u * 16);
            size_t go = base + DD + (size_t)(kt * 64 + r) * rowstride + u * 8;
            cpa16(KHs + so, qh + go);
            cpa16(KLs + so, ql + go);
        }
        CP_COMMIT();
    };
    auto load_v = [&](int kt) {
        #pragma unroll
        for (int i = 0; i < 2; i++) {
            int id = tid + i * 256;
            int r = id >> 3, u = id & 7;
            uint32_t so = SW128(r * 128 + u * 16);
            size_t go = base + 2 * DD + (size_t)(kt * 64 + r) * rowstride + u * 8;
            cpa16(VHs + so, qh + go);
            cpa16(VLs + so, ql + go);
        }
        CP_COMMIT();
    };

    // Q tile load (128 rows, own commit group), then K0, V0
    {
        #pragma unroll
        for (int i = 0; i < 4; i++) {
            int id = tid + i * 256;                 // 0..1023
            int r = id >> 3, u = id & 7;
            uint32_t so = SW128(r * 128 + u * 16);
            size_t go = base + (size_t)(t0 + r) * rowstride + u * 8;
            cpa16(QHs + so, qh + go);
            cpa16(QLs + so, ql + go);
        }
        CP_COMMIT();
    }
    load_k(0);
    load_v(0);

    float o[8][4];
    #pragma unroll
    for (int nf = 0; nf < 8; nf++)
        #pragma unroll
        for (int i = 0; i < 4; i++) o[nf][i] = 0.f;
    float m[2] = {-1e30f, -1e30f};
    float l2s[2] = {0.f, 0.f};

    for (int kt = 0; kt < NT; kt++) {
        // wait for K(kt) (V(kt) may still be in flight)
        CP_WAIT(1);
        __syncthreads();

        // ---- S = Q @ K^T  (warp: 16 q-rows x 64 keys) ----
        float sc[8][4];
        #pragma unroll
        for (int nf = 0; nf < 8; nf++)
            #pragma unroll
            for (int i = 0; i < 4; i++) sc[nf][i] = 0.f;

        #pragma unroll
        for (int ks = 0; ks < 4; ks++) {
            unsigned qfh[4], qfl[4];
            {
                int row = 16 * w + tlo * 8 + lr;
                uint32_t so = SW128(row * 128 + ks * 32 + thi * 16);
                ldsm4(qfh[0], qfh[1], qfh[2], qfh[3], QHs + so);
                ldsm4(qfl[0], qfl[1], qfl[2], qfl[3], QLs + so);
            }
            #pragma unroll
            for (int np = 0; np < 4; np++) {
                int row = np * 16 + thi * 8 + lr;
                uint32_t so = SW128(row * 128 + ks * 32 + tlo * 16);
                unsigned kh[4], kl[4];
                ldsm4(kh[0], kh[1], kh[2], kh[3], KHs + so);
                ldsm4(kl[0], kl[1], kl[2], kl[3], KLs + so);
                #pragma unroll
                for (int half = 0; half < 2; half++) {
                    int nf = np * 2 + half;
                    unsigned b0h = kh[2 * half], b1h = kh[2 * half + 1];
                    unsigned b0l = kl[2 * half], b1l = kl[2 * half + 1];
                    mma16(sc[nf], qfh[0], qfh[1], qfh[2], qfh[3], b0h, b1h);
                    mma16(sc[nf], qfh[0], qfh[1], qfh[2], qfh[3], b0l, b1l);
                    mma16(sc[nf], qfl[0], qfl[1], qfl[2], qfl[3], b0h, b1h);
                }
            }
        }

        __syncthreads();                 // all warps done reading K buffer
        if (kt + 1 < NT) load_k(kt + 1); // K(kt+1) hides behind softmax + PV

        // ---- online softmax (registers only) ----
        #pragma unroll
        for (int r = 0; r < 2; r++) {
            float mx = -1e30f;
            #pragma unroll
            for (int nf = 0; nf < 8; nf++)
                mx = fmaxf(mx, fmaxf(sc[nf][2 * r], sc[nf][2 * r + 1]));
            mx = fmaxf(mx, __shfl_xor_sync(0xffffffffu, mx, 1));
            mx = fmaxf(mx, __shfl_xor_sync(0xffffffffu, mx, 2));
            float mn = fmaxf(m[r], mx);
            float alpha = __expf(m[r] - mn);
            m[r] = mn;
            float sum = 0.f;
            #pragma unroll
            for (int nf = 0; nf < 8; nf++) {
                float p0 = __expf(sc[nf][2 * r] - mn);
                float p1 = __expf(sc[nf][2 * r + 1] - mn);
                sc[nf][2 * r] = p0;
                sc[nf][2 * r + 1] = p1;
                sum += p0 + p1;
            }
            sum += __shfl_xor_sync(0xffffffffu, sum, 1);
            sum += __shfl_xor_sync(0xffffffffu, sum, 2);
            l2s[r] = l2s[r] * alpha + sum;
            #pragma unroll
            for (int nf = 0; nf < 8; nf++) {
                o[nf][2 * r] *= alpha;
                o[nf][2 * r + 1] *= alpha;
            }
        }

        // wait for V(kt); one group (K(kt+1)) may remain outstanding
        if (kt + 1 < NT) CP_WAIT(1); else CP_WAIT(0);
        __syncthreads();

        // ---- O += P @ V ----
        #pragma unroll
        for (int ks2 = 0; ks2 < 4; ks2++) {
            unsigned pa_h[4], pa_l[4];
            #pragma unroll
            for (int half = 0; half < 2; half++) {
                const float* s4 = sc[2 * ks2 + half];
                __nv_bfloat16 h0, l0, h1, l1, h2, l2, h3, l3;
                bf16split(s4[0], h0, l0);
                bf16split(s4[1], h1, l1);
                bf16split(s4[2], h2, l2);
                bf16split(s4[3], h3, l3);
                pa_h[2 * half]     = pack2(h0, h1);
                pa_h[2 * half + 1] = pack2(h2, h3);
                pa_l[2 * half]     = pack2(l0, l1);
                pa_l[2 * half + 1] = pack2(l2, l3);
            }
            #pragma unroll
            for (int np = 0; np < 4; np++) {
                int vr = ks2 * 16 + tlo * 8 + lr;
                uint32_t so = SW128(vr * 128 + np * 32 + thi * 16);
                unsigned vh[4], vl[4];
                ldsm4t(vh[0], vh[1], vh[2], vh[3], VHs + so);
                ldsm4t(vl[0], vl[1], vl[2], vl[3], VLs + so);
                #pragma unroll
                for (int half = 0; half < 2; half++) {
                    int nfo = np * 2 + half;
                    unsigned b0h = vh[2 * half], b1h = vh[2 * half + 1];
                    unsigned b0l = vl[2 * half], b1l = vl[2 * half + 1];
                    mma16(o[nfo], pa_h[0], pa_h[1], pa_h[2], pa_h[3], b0h, b1h);
                    mma16(o[nfo], pa_h[0], pa_h[1], pa_h[2], pa_h[3], b0l, b1l);
                    mma16(o[nfo], pa_l[0], pa_l[1], pa_l[2], pa_l[3], b0h, b1h);
                }
            }
        }

        __syncthreads();                 // all warps done reading V buffer
        if (kt + 1 < NT) load_v(kt + 1); // V(kt+1) hides behind next S + softmax
    }

    // normalize + write bf16 hi/lo
    #pragma unroll
    for (int r = 0; r < 2; r++) {
        float inv = 1.f / l2s[r];
        int row = t0 + 16 * w + g + 8 * r;
        #pragma unroll
        for (int nf = 0; nf < 8; nf++) {
            int col = h * HDD + nf * 8 + 2 * t;
            float v0 = o[nf][2 * r] * inv;
            float v1 = o[nf][2 * r + 1] * inv;
            __nv_bfloat16 h0, l0, h1, l1;
            bf16split(v0, h0, l0);
            bf16split(v1, h1, l1);
            size_t idx = (size_t)(b * TT + row) * DD + col;
            *reinterpret_cast<unsigned*>(&outH[idx]) = pack2(h0, h1);
            *reinterpret_cast<unsigned*>(&outL[idx]) = pack2(l0, l1);
        }
    }
}

// ---------------------------------------------------------------------------
extern "C" void kernel_launch(void* const* d_in, const int* in_sizes, int n_in,
                              void* d_out, int out_size)
{
    const float* x     = (const float*)d_in[0];
    const float* w_qkv = (const float*)d_in[1];
    const float* b_qkv = (const float*)d_in[2];
    const float* w_out = (const float*)d_in[3];
    const float* b_out = (const float*)d_in[4];
    float* out = (float*)d_out;

    __nv_bfloat16 *xh, *xl, *wqh, *wql, *woh, *wol, *qkvh, *qkvl, *ah, *al;
    cudaGetSymbolAddress((void**)&xh,   g_xh);
    cudaGetSymbolAddress((void**)&xl,   g_xl);
    cudaGetSymbolAddress((void**)&wqh,  g_wqkvT_h);
    cudaGetSymbolAddress((void**)&wql,  g_wqkvT_l);
    cudaGetSymbolAddress((void**)&woh,  g_woutT_h);
    cudaGetSymbolAddress((void**)&wol,  g_woutT_l);
    cudaGetSymbolAddress((void**)&qkvh, g_qkvH);
    cudaGetSymbolAddress((void**)&qkvl, g_qkvL);
    cudaGetSymbolAddress((void**)&ah,   g_attnH);
    cudaGetSymbolAddress((void**)&al,   g_attnL);

    const int GEMM_SMEM = 3 * 32768;   // 96 KB, 3-stage
    cudaFuncSetAttribute(gemm_mma_kernel,
                         cudaFuncAttributeMaxDynamicSharedMemorySize, GEMM_SMEM);
    const int ATTN_SMEM = 65536;       // 64 KB
    cudaFuncSetAttribute(attn_tc_kernel,
                         cudaFuncAttributeMaxDynamicSharedMemorySize, ATTN_SMEM);

    // Pre-pass: split X; transpose+split weights
    {
        int n4 = BB * TT * DD / 4;
        split_kernel<<<(n4 + 255) / 256, 256>>>(x, xh, xl, n4);
        dim3 bt(32, 8);
        transpose_split_kernel<<<dim3(3 * DD / 32, DD / 32), bt>>>(w_qkv, wqh, wql, DD, 3 * DD);
        transpose_split_kernel<<<dim3(DD / 32, DD / 32), bt>>>(w_out, woh, wol, DD, DD);
    }

    // 1) QKV projection -> bf16 hi/lo (Q pre-scaled by 0.125)
    gemm_mma_kernel<<<dim3(3 * DD / 128, BB * TT / 128), 256, GEMM_SMEM>>>(
        xh, xl, wqh, wql, b_qkv, nullptr, qkvh, qkvl, 3 * DD, DD, 1);

    // 2) Attention -> bf16 hi/lo (128-row Q tiles)
    attn_tc_kernel<<<dim3(TT / 128, HH, BB), 256, ATTN_SMEM>>>(qkvh, qkvl, ah, al);

    // 3) Output projection -> fp32 d_out
    gemm_mma_kernel<<<dim3(DD / 128, BB * TT / 128), 256, GEMM_SMEM>>>(
        ah, al, woh, wol, b_out, out, nullptr, nullptr, DD, DD, 0);
}

// round 15
// speedup vs baseline: 1.5616x; 1.5616x over previous
#include <cuda_runtime.h>
#include <cuda_bf16.h>
#include <cstdint>
#include <math.h>

#define BB 16
#define TT 1024
#define DD 1024
#define HH 16
#define HDD 64

// ---------------------------------------------------------------------------
// Scratch (allocation-free rule: __device__ globals)
// ---------------------------------------------------------------------------
__device__ __nv_bfloat16 g_xh[BB * TT * DD];        // X hi
__device__ __nv_bfloat16 g_xl[BB * TT * DD];        // X lo
__device__ __nv_bfloat16 g_wqkvT_h[3 * DD * DD];    // WqkvT [3D][D] hi
__device__ __nv_bfloat16 g_wqkvT_l[3 * DD * DD];
__device__ __nv_bfloat16 g_woutT_h[DD * DD];        // WoutT [D][D] hi
__device__ __nv_bfloat16 g_woutT_l[DD * DD];
__device__ __nv_bfloat16 g_qkvH[BB * TT * 3 * DD];  // qkv hi (Q pre-scaled)
__device__ __nv_bfloat16 g_qkvL[BB * TT * 3 * DD];  // qkv lo
__device__ __nv_bfloat16 g_attnH[BB * TT * DD];     // attention out hi
__device__ __nv_bfloat16 g_attnL[BB * TT * DD];     // attention out lo

// ---------------------------------------------------------------------------
// helpers
// ---------------------------------------------------------------------------
__device__ __forceinline__ unsigned ssa(const void* p) {
    return (unsigned)__cvta_generic_to_shared(p);
}
__device__ __forceinline__ void bf16split(float x, __nv_bfloat16& hi, __nv_bfloat16& lo) {
    hi = __float2bfloat16(x);
    lo = __float2bfloat16(x - __bfloat162float(hi));
}
__device__ __forceinline__ unsigned pack2(__nv_bfloat16 a, __nv_bfloat16 b) {
    __nv_bfloat162 v(a, b);
    return *reinterpret_cast<unsigned*>(&v);
}
__device__ __forceinline__ void ldsm4(unsigned& r0, unsigned& r1,
                                      unsigned& r2, unsigned& r3, unsigned a) {
    asm volatile("ldmatrix.sync.aligned.m8n8.x4.shared.b16 {%0,%1,%2,%3}, [%4];"
                 : "=r"(r0), "=r"(r1), "=r"(r2), "=r"(r3) : "r"(a));
}
__device__ __forceinline__ void ldsm4t(unsigned& r0, unsigned& r1,
                                       unsigned& r2, unsigned& r3, unsigned a) {
    asm volatile("ldmatrix.sync.aligned.m8n8.x4.trans.shared.b16 {%0,%1,%2,%3}, [%4];"
                 : "=r"(r0), "=r"(r1), "=r"(r2), "=r"(r3) : "r"(a));
}
__device__ __forceinline__ void mma16(float* c,
                                      unsigned a0, unsigned a1, unsigned a2, unsigned a3,
                                      unsigned b0, unsigned b1) {
    asm volatile(
        "mma.sync.aligned.m16n8k16.row.col.f32.bf16.bf16.f32 "
        "{%0,%1,%2,%3}, {%4,%5,%6,%7}, {%8,%9}, {%0,%1,%2,%3};"
        : "+f"(c[0]), "+f"(c[1]), "+f"(c[2]), "+f"(c[3])
        : "r"(a0), "r"(a1), "r"(a2), "r"(a3), "r"(b0), "r"(b1));
}
__device__ __forceinline__ void cpa16(uint32_t s, const void* g) {
    asm volatile("cp.async.cg.shared.global [%0], [%1], 16;" :: "r"(s), "l"(g));
}
#define CP_COMMIT() asm volatile("cp.async.commit_group;" ::: "memory")
#define CP_WAIT(n)  asm volatile("cp.async.wait_group %0;" :: "n"(n) : "memory")

#define SW128(off) ((off) ^ (((off) >> 3) & 0x70))
#define SW64B(off) ((off) ^ (((off) >> 3) & 0x30))

// ---------------------------------------------------------------------------
// Pre-pass 1: split fp32 -> bf16 hi/lo
// ---------------------------------------------------------------------------
__global__ void split_kernel(const float* __restrict__ X,
                             __nv_bfloat16* __restrict__ H,
                             __nv_bfloat16* __restrict__ L, int n4)
{
    int i = blockIdx.x * blockDim.x + threadIdx.x;
    if (i >= n4) return;
    float4 v = reinterpret_cast<const float4*>(X)[i];
    float f[4] = {v.x, v.y, v.z, v.w};
    __nv_bfloat16 h[4], l[4];
    #pragma unroll
    for (int j = 0; j < 4; j++) bf16split(f[j], h[j], l[j]);
    reinterpret_cast<uint2*>(H)[i] = make_uint2(pack2(h[0], h[1]), pack2(h[2], h[3]));
    reinterpret_cast<uint2*>(L)[i] = make_uint2(pack2(l[0], l[1]), pack2(l[2], l[3]));
}

// ---------------------------------------------------------------------------
// Pre-pass 2: W [K][N] fp32 -> WT [N][K] bf16 hi/lo
// ---------------------------------------------------------------------------
__global__ void transpose_split_kernel(const float* __restrict__ W,
                                       __nv_bfloat16* __restrict__ Th,
                                       __nv_bfloat16* __restrict__ Tl,
                                       int K, int N)
{
    __shared__ float t[32][33];
    int n0 = blockIdx.x * 32, k0 = blockIdx.y * 32;
    int tx = threadIdx.x, ty = threadIdx.y;
    #pragma unroll
    for (int i = 0; i < 32; i += 8)
        t[ty + i][tx] = W[(size_t)(k0 + ty + i) * N + n0 + tx];
    __syncthreads();
    #pragma unroll
    for (int i = 0; i < 32; i += 8) {
        float v = t[tx][ty + i];
        __nv_bfloat16 h, l;
        bf16split(v, h, l);
        Th[(size_t)(n0 + ty + i) * K + k0 + tx] = h;
        Tl[(size_t)(n0 + ty + i) * K + k0 + tx] = l;
    }
}

// ---------------------------------------------------------------------------
// bf16x2-split mma.sync GEMM, 3-stage cp.async pipeline, SW64-swizzled tiles,
// SINGLE barrier per chunk: wait(1) -> sync -> load(cc+2) -> compute(cc).
// The sync at iter cc proves all warps finished iter cc-1, so buffer
// (cc+2)%3 == (cc-1)%3 is safe to overwrite. 32 barriers/CTA (was 64).
// ---------------------------------------------------------------------------
__global__ void __launch_bounds__(256, 2)
gemm_mma_kernel(const __nv_bfloat16* __restrict__ Ah,
                const __nv_bfloat16* __restrict__ Al,
                const __nv_bfloat16* __restrict__ Bh,
                const __nv_bfloat16* __restrict__ Bl,
                const float* __restrict__ bias,
                float* __restrict__ Cf,
                __nv_bfloat16* __restrict__ Ch,
                __nv_bfloat16* __restrict__ Cl,
                int N, int K, int mode)
{
    extern __shared__ char dsm[];
    constexpr int STAGE = 32768;          // 4 arrays * 8192 B
    const uint32_t sb0 = ssa(dsm);

    const int tid = threadIdx.x;
    const int wid = tid >> 5;
    const int wr = wid & 3;
    const int wc = wid >> 2;
    const int lane = tid & 31;
    const int g = lane >> 2;
    const int t = lane & 3;
    const int lr  = lane & 7;
    const int tlo = (lane >> 3) & 1;
    const int thi = lane >> 4;
    const int blockRow = blockIdx.y * 128;
    const int blockCol = blockIdx.x * 128;
    const int NC = K / 32;                // 32 chunks

    float c[2][8][4];
    #pragma unroll
    for (int mf = 0; mf < 2; mf++)
        #pragma unroll
        for (int nf = 0; nf < 8; nf++)
            #pragma unroll
            for (int i = 0; i < 4; i++) c[mf][nf][i] = 0.f;

    auto load_chunk = [&](int cc) {
        const uint32_t sb = sb0 + (cc % 3) * STAGE;
        const int kt = cc * 32;
        #pragma unroll
        for (int i = 0; i < 2; i++) {
            int id = tid + i * 256;           // 0..511
            int row = id >> 2, u = id & 3;    // 128 rows x 4 x 16B
            uint32_t off = SW64B(row * 64 + u * 16);
            size_t ga = (size_t)(blockRow + row) * K + kt + u * 8;
            size_t gb = (size_t)(blockCol + row) * K + kt + u * 8;
            cpa16(sb + off,         Ah + ga);
            cpa16(sb +  8192 + off, Al + ga);
            cpa16(sb + 16384 + off, Bh + gb);
            cpa16(sb + 24576 + off, Bl + gb);
        }
        CP_COMMIT();
    };

    load_chunk(0);
    load_chunk(1);

    for (int cc = 0; cc < NC; cc++) {
        if (cc + 1 < NC) CP_WAIT(1); else CP_WAIT(0);
        __syncthreads();
        if (cc + 2 < NC) load_chunk(cc + 2);

        const uint32_t sb = sb0 + (cc % 3) * STAGE;
        #pragma unroll
        for (int ks = 0; ks < 2; ks++) {
            unsigned ah[2][4], al_[2][4];
            #pragma unroll
            for (int mf = 0; mf < 2; mf++) {
                int row = wr * 32 + mf * 16 + tlo * 8 + lr;
                uint32_t off = SW64B(row * 64 + ks * 32 + thi * 16);
                ldsm4(ah[mf][0], ah[mf][1], ah[mf][2], ah[mf][3], sb + off);
                ldsm4(al_[mf][0], al_[mf][1], al_[mf][2], al_[mf][3], sb + 8192 + off);
            }
            #pragma unroll
            for (int np = 0; np < 4; np++) {
                int nrow = wc * 64 + np * 16 + thi * 8 + lr;
                uint32_t off = SW64B(nrow * 64 + ks * 32 + tlo * 16);
                unsigned bh[4], bl[4];
                ldsm4(bh[0], bh[1], bh[2], bh[3], sb + 16384 + off);
                ldsm4(bl[0], bl[1], bl[2], bl[3], sb + 24576 + off);
                #pragma unroll
                for (int half = 0; half < 2; half++) {
                    int nf = np * 2 + half;
                    unsigned b0h = bh[2 * half], b1h = bh[2 * half + 1];
                    unsigned b0l = bl[2 * half], b1l = bl[2 * half + 1];
                    #pragma unroll
                    for (int mf = 0; mf < 2; mf++) {
                        mma16(c[mf][nf], ah[mf][0], ah[mf][1], ah[mf][2], ah[mf][3], b0h, b1h);
                        mma16(c[mf][nf], ah[mf][0], ah[mf][1], ah[mf][2], ah[mf][3], b0l, b1l);
                        mma16(c[mf][nf], al_[mf][0], al_[mf][1], al_[mf][2], al_[mf][3], b0h, b1h);
                    }
                }
            }
        }
    }

    // epilogue
    const float qs = (mode == 1 && blockCol < DD) ? 0.125f : 1.0f;
    #pragma unroll
    for (int mf = 0; mf < 2; mf++) {
        int row = blockRow + wr * 32 + mf * 16 + g;
        #pragma unroll
        for (int nf = 0; nf < 8; nf++) {
            int col = blockCol + wc * 64 + nf * 8 + 2 * t;
            float bx = bias[col], by = bias[col + 1];
            float v0 = (c[mf][nf][0] + bx) * qs;
            float v1 = (c[mf][nf][1] + by) * qs;
            float v2 = (c[mf][nf][2] + bx) * qs;
            float v3 = (c[mf][nf][3] + by) * qs;
            if (mode == 0) {
                *reinterpret_cast<float2*>(&Cf[(size_t)row * N + col]) = make_float2(v0, v1);
                *reinterpret_cast<float2*>(&Cf[(size_t)(row + 8) * N + col]) = make_float2(v2, v3);
            } else {
                __nv_bfloat16 h0, l0, h1, l1;
                bf16split(v0, h0, l0); bf16split(v1, h1, l1);
                *reinterpret_cast<unsigned*>(&Ch[(size_t)row * N + col]) = pack2(h0, h1);
                *reinterpret_cast<unsigned*>(&Cl[(size_t)row * N + col]) = pack2(l0, l1);
                bf16split(v2, h0, l0); bf16split(v3, h1, l1);
                *reinterpret_cast<unsigned*>(&Ch[(size_t)(row + 8) * N + col]) = pack2(h0, h1);
                *reinterpret_cast<unsigned*>(&Cl[(size_t)(row + 8) * N + col]) = pack2(l0, l1);
            }
        }
    }
}

// ---------------------------------------------------------------------------
// Flash attention, bf16 3-term split, 64-row Q tiles (round-12 proven config).
// Block = 64 q rows of one (b,h); 128 threads = 4 warps; 48 KB smem, 4 CTAs/SM.
// Split K/V commit groups:
// wait K -> S -> sync -> issue K(kt+1) -> softmax -> wait V -> PV -> issue V(kt+1).
// ---------------------------------------------------------------------------
__global__ void __launch_bounds__(128, 4)
attn_tc_kernel(const __nv_bfloat16* __restrict__ qh,
               const __nv_bfloat16* __restrict__ ql,
               __nv_bfloat16* __restrict__ outH,
               __nv_bfloat16* __restrict__ outL)
{
    extern __shared__ char asm_[];
    const uint32_t QHs = ssa(asm_);
    const uint32_t QLs = QHs + 8192;
    const uint32_t KHs = QHs + 16384;
    const uint32_t KLs = QHs + 24576;
    const uint32_t VHs = QHs + 32768;
    const uint32_t VLs = QHs + 40960;

    const int b = blockIdx.z;
    const int h = blockIdx.y;
    const int qt = blockIdx.x;
    const int tid = threadIdx.x;
    const int w = tid >> 5;
    const int lane = tid & 31;
    const int g = lane >> 2;
    const int t = lane & 3;
    const int lr  = lane & 7;
    const int tlo = (lane >> 3) & 1;
    const int thi = lane >> 4;
    const int t0 = qt * 64;
    const int NT = TT / 64;

    const size_t rowstride = 3 * DD;
    const size_t base = (size_t)(b * TT) * rowstride + h * HDD;

    auto load_k = [&](int kt) {
        #pragma unroll
        for (int i = 0; i < 4; i++) {
            int id = tid + i * 128;                 // 0..511
            int r = id >> 3, u = id & 7;
            uint32_t so = SW128(r * 128 + u * 16);
            size_t go = base + DD + (size_t)(kt * 64 + r) * rowstride + u * 8;
            cpa16(KHs + so, qh + go);
            cpa16(KLs + so, ql + go);
        }
        CP_COMMIT();
    };
    auto load_v = [&](int kt) {
        #pragma unroll
        for (int i = 0; i < 4; i++) {
            int id = tid + i * 128;
            int r = id >> 3, u = id & 7;
            uint32_t so = SW128(r * 128 + u * 16);
            size_t go = base + 2 * DD + (size_t)(kt * 64 + r) * rowstride + u * 8;
            cpa16(VHs + so, qh + go);
            cpa16(VLs + so, ql + go);
        }
        CP_COMMIT();
    };

    // Q tile load (own commit group), then K0, V0
    {
        #pragma unroll
        for (int i = 0; i < 4; i++) {
            int id = tid + i * 128;
            int r = id >> 3, u = id & 7;
            uint32_t so = SW128(r * 128 + u * 16);
            size_t go = base + (size_t)(t0 + r) * rowstride + u * 8;
            cpa16(QHs + so, qh + go);
            cpa16(QLs + so, ql + go);
        }
        CP_COMMIT();
    }
    load_k(0);
    load_v(0);

    float o[8][4];
    #pragma unroll
    for (int nf = 0; nf < 8; nf++)
        #pragma unroll
        for (int i = 0; i < 4; i++) o[nf][i] = 0.f;
    float m[2] = {-1e30f, -1e30f};
    float l2s[2] = {0.f, 0.f};

    for (int kt = 0; kt < NT; kt++) {
        // wait for K(kt) (V(kt) may still be in flight)
        CP_WAIT(1);
        __syncthreads();

        // ---- S = Q @ K^T ----
        float sc[8][4];
        #pragma unroll
        for (int nf = 0; nf < 8; nf++)
            #pragma unroll
            for (int i = 0; i < 4; i++) sc[nf][i] = 0.f;

        #pragma unroll
        for (int ks = 0; ks < 4; ks++) {
            unsigned qfh[4], qfl[4];
            {
                int row = 16 * w + tlo * 8 + lr;
                uint32_t so = SW128(row * 128 + ks * 32 + thi * 16);
                ldsm4(qfh[0], qfh[1], qfh[2], qfh[3], QHs + so);
                ldsm4(qfl[0], qfl[1], qfl[2], qfl[3], QLs + so);
            }
            #pragma unroll
            for (int np = 0; np < 4; np++) {
                int row = np * 16 + thi * 8 + lr;
                uint32_t so = SW128(row * 128 + ks * 32 + tlo * 16);
                unsigned kh[4], kl[4];
                ldsm4(kh[0], kh[1], kh[2], kh[3], KHs + so);
                ldsm4(kl[0], kl[1], kl[2], kl[3], KLs + so);
                #pragma unroll
                for (int half = 0; half < 2; half++) {
                    int nf = np * 2 + half;
                    unsigned b0h = kh[2 * half], b1h = kh[2 * half + 1];
                    unsigned b0l = kl[2 * half], b1l = kl[2 * half + 1];
                    mma16(sc[nf], qfh[0], qfh[1], qfh[2], qfh[3], b0h, b1h);
                    mma16(sc[nf], qfh[0], qfh[1], qfh[2], qfh[3], b0l, b1l);
                    mma16(sc[nf], qfl[0], qfl[1], qfl[2], qfl[3], b0h, b1h);
                }
            }
        }

        __syncthreads();                 // all warps done reading K buffer
        if (kt + 1 < NT) load_k(kt + 1); // K(kt+1) hides behind softmax + PV

        // ---- online softmax (registers only) ----
        #pragma unroll
        for (int r = 0; r < 2; r++) {
            float mx = -1e30f;
            #pragma unroll
            for (int nf = 0; nf < 8; nf++)
                mx = fmaxf(mx, fmaxf(sc[nf][2 * r], sc[nf][2 * r + 1]));
            mx = fmaxf(mx, __shfl_xor_sync(0xffffffffu, mx, 1));
            mx = fmaxf(mx, __shfl_xor_sync(0xffffffffu, mx, 2));
            float mn = fmaxf(m[r], mx);
            float alpha = __expf(m[r] - mn);
            m[r] = mn;
            float sum = 0.f;
            #pragma unroll
            for (int nf = 0; nf < 8; nf++) {
                float p0 = __expf(sc[nf][2 * r] - mn);
                float p1 = __expf(sc[nf][2 * r + 1] - mn);
                sc[nf][2 * r] = p0;
                sc[nf][2 * r + 1] = p1;
                sum += p0 + p1;
            }
            sum += __shfl_xor_sync(0xffffffffu, sum, 1);
            sum += __shfl_xor_sync(0xffffffffu, sum, 2);
            l2s[r] = l2s[r] * alpha + sum;
            #pragma unroll
            for (int nf = 0; nf < 8; nf++) {
                o[nf][2 * r] *= alpha;
                o[nf][2 * r + 1] *= alpha;
            }
        }

        // wait for V(kt); one group (K(kt+1)) may remain outstanding
        if (kt + 1 < NT) CP_WAIT(1); else CP_WAIT(0);
        __syncthreads();

        // ---- O += P @ V ----
        #pragma unroll
        for (int ks2 = 0; ks2 < 4; ks2++) {
            unsigned pa_h[4], pa_l[4];
            #pragma unroll
            for (int half = 0; half < 2; half++) {
                const float* s4 = sc[2 * ks2 + half];
                __nv_bfloat16 h0, l0, h1, l1, h2, l2, h3, l3;
                bf16split(s4[0], h0, l0);
                bf16split(s4[1], h1, l1);
                bf16split(s4[2], h2, l2);
                bf16split(s4[3], h3, l3);
                pa_h[2 * half]     = pack2(h0, h1);
                pa_h[2 * half + 1] = pack2(h2, h3);
                pa_l[2 * half]     = pack2(l0, l1);
                pa_l[2 * half + 1] = pack2(l2, l3);
            }
            #pragma unroll
            for (int np = 0; np < 4; np++) {
                int vr = ks2 * 16 + tlo * 8 + lr;
                uint32_t so = SW128(vr * 128 + np * 32 + thi * 16);
                unsigned vh[4], vl[4];
                ldsm4t(vh[0], vh[1], vh[2], vh[3], VHs + so);
                ldsm4t(vl[0], vl[1], vl[2], vl[3], VLs + so);
                #pragma unroll
                for (int half = 0; half < 2; half++) {
                    int nfo = np * 2 + half;
                    unsigned b0h = vh[2 * half], b1h = vh[2 * half + 1];
                    unsigned b0l = vl[2 * half], b1l = vl[2 * half + 1];
                    mma16(o[nfo], pa_h[0], pa_h[1], pa_h[2], pa_h[3], b0h, b1h);
                    mma16(o[nfo], pa_h[0], pa_h[1], pa_h[2], pa_h[3], b0l, b1l);
                    mma16(o[nfo], pa_l[0], pa_l[1], pa_l[2], pa_l[3], b0h, b1h);
                }
            }
        }

        __syncthreads();                 // all warps done reading V buffer
        if (kt + 1 < NT) load_v(kt + 1); // V(kt+1) hides behind next S + softmax
    }

    // normalize + write bf16 hi/lo
    #pragma unroll
    for (int r = 0; r < 2; r++) {
        float inv = 1.f / l2s[r];
        int row = t0 + 16 * w + g + 8 * r;
        #pragma unroll
        for (int nf = 0; nf < 8; nf++) {
            int col = h * HDD + nf * 8 + 2 * t;
            float v0 = o[nf][2 * r] * inv;
            float v1 = o[nf][2 * r + 1] * inv;
            __nv_bfloat16 h0, l0, h1, l1;
            bf16split(v0, h0, l0);
            bf16split(v1, h1, l1);
            size_t idx = (size_t)(b * TT + row) * DD + col;
            *reinterpret_cast<unsigned*>(&outH[idx]) = pack2(h0, h1);
            *reinterpret_cast<unsigned*>(&outL[idx]) = pack2(l0, l1);
        }
    }
}

// ---------------------------------------------------------------------------
extern "C" void kernel_launch(void* const* d_in, const int* in_sizes, int n_in,
                              void* d_out, int out_size)
{
    const float* x     = (const float*)d_in[0];
    const float* w_qkv = (const float*)d_in[1];
    const float* b_qkv = (const float*)d_in[2];
    const float* w_out = (const float*)d_in[3];
    const float* b_out = (const float*)d_in[4];
    float* out = (float*)d_out;

    __nv_bfloat16 *xh, *xl, *wqh, *wql, *woh, *wol, *qkvh, *qkvl, *ah, *al;
    cudaGetSymbolAddress((void**)&xh,   g_xh);
    cudaGetSymbolAddress((void**)&xl,   g_xl);
    cudaGetSymbolAddress((void**)&wqh,  g_wqkvT_h);
    cudaGetSymbolAddress((void**)&wql,  g_wqkvT_l);
    cudaGetSymbolAddress((void**)&woh,  g_woutT_h);
    cudaGetSymbolAddress((void**)&wol,  g_woutT_l);
    cudaGetSymbolAddress((void**)&qkvh, g_qkvH);
    cudaGetSymbolAddress((void**)&qkvl, g_qkvL);
    cudaGetSymbolAddress((void**)&ah,   g_attnH);
    cudaGetSymbolAddress((void**)&al,   g_attnL);

    const int GEMM_SMEM = 3 * 32768;   // 96 KB, 3-stage
    cudaFuncSetAttribute(gemm_mma_kernel,
                         cudaFuncAttributeMaxDynamicSharedMemorySize, GEMM_SMEM);
    const int ATTN_SMEM = 6 * 8192;    // 48 KB
    cudaFuncSetAttribute(attn_tc_kernel,
                         cudaFuncAttributeMaxDynamicSharedMemorySize, ATTN_SMEM);

    // Pre-pass: split X; transpose+split weights
    {
        int n4 = BB * TT * DD / 4;
        split_kernel<<<(n4 + 255) / 256, 256>>>(x, xh, xl, n4);
        dim3 bt(32, 8);
        transpose_split_kernel<<<dim3(3 * DD / 32, DD / 32), bt>>>(w_qkv, wqh, wql, DD, 3 * DD);
        transpose_split_kernel<<<dim3(DD / 32, DD / 32), bt>>>(w_out, woh, wol, DD, DD);
    }

    // 1) QKV projection -> bf16 hi/lo (Q pre-scaled by 0.125)
    gemm_mma_kernel<<<dim3(3 * DD / 128, BB * TT / 128), 256, GEMM_SMEM>>>(
        xh, xl, wqh, wql, b_qkv, nullptr, qkvh, qkvl, 3 * DD, DD, 1);

    // 2) Attention -> bf16 hi/lo (64-row Q tiles, proven config)
    attn_tc_kernel<<<dim3(TT / 64, HH, BB), 128, ATTN_SMEM>>>(qkvh, qkvl, ah, al);

    // 3) Output projection -> fp32 d_out
    gemm_mma_kernel<<<dim3(DD / 128, BB * TT / 128), 256, GEMM_SMEM>>>(
        ah, al, woh, wol, b_out, out, nullptr, nullptr, DD, DD, 0);
}

// round 16
// speedup vs baseline: 2.1854x; 1.3994x over previous
#include <cuda_runtime.h>
#include <cuda_fp16.h>
#include <cstdint>
#include <math.h>

#define BB 16
#define TT 1024
#define DD 1024
#define HH 16
#define HDD 64

// ---------------------------------------------------------------------------
// Scratch (allocation-free rule: __device__ globals)
// ---------------------------------------------------------------------------
__device__ __half g_xh[BB * TT * DD];        // X hi
__device__ __half g_xl[BB * TT * DD];        // X lo
__device__ __half g_wqkvT_h[3 * DD * DD];    // WqkvT [3D][D] (rounded)
__device__ __half g_woutT_h[DD * DD];        // WoutT [D][D] (rounded)
__device__ __half g_qkvH[BB * TT * 3 * DD];  // qkv hi (Q pre-scaled)
__device__ __half g_qkvL[BB * TT * 3 * DD];  // qkv lo (only Q region used)
__device__ __half g_attnH[BB * TT * DD];     // attention out hi
__device__ __half g_attnL[BB * TT * DD];     // attention out lo

// ---------------------------------------------------------------------------
// helpers
// ---------------------------------------------------------------------------
__device__ __forceinline__ unsigned ssa(const void* p) {
    return (unsigned)__cvta_generic_to_shared(p);
}
__device__ __forceinline__ void f16split(float x, __half& hi, __half& lo) {
    hi = __float2half_rn(x);
    lo = __float2half_rn(x - __half2float(hi));
}
__device__ __forceinline__ unsigned pack2h(__half a, __half b) {
    __half2 v = __halves2half2(a, b);
    return *reinterpret_cast<unsigned*>(&v);
}
__device__ __forceinline__ void ldsm4(unsigned& r0, unsigned& r1,
                                      unsigned& r2, unsigned& r3, unsigned a) {
    asm volatile("ldmatrix.sync.aligned.m8n8.x4.shared.b16 {%0,%1,%2,%3}, [%4];"
                 : "=r"(r0), "=r"(r1), "=r"(r2), "=r"(r3) : "r"(a));
}
__device__ __forceinline__ void ldsm4t(unsigned& r0, unsigned& r1,
                                       unsigned& r2, unsigned& r3, unsigned a) {
    asm volatile("ldmatrix.sync.aligned.m8n8.x4.trans.shared.b16 {%0,%1,%2,%3}, [%4];"
                 : "=r"(r0), "=r"(r1), "=r"(r2), "=r"(r3) : "r"(a));
}
// m16n8k16 fp16 MMA, fp32 accumulate
__device__ __forceinline__ void mma16(float* c,
                                      unsigned a0, unsigned a1, unsigned a2, unsigned a3,
                                      unsigned b0, unsigned b1) {
    asm volatile(
        "mma.sync.aligned.m16n8k16.row.col.f32.f16.f16.f32 "
        "{%0,%1,%2,%3}, {%4,%5,%6,%7}, {%8,%9}, {%0,%1,%2,%3};"
        : "+f"(c[0]), "+f"(c[1]), "+f"(c[2]), "+f"(c[3])
        : "r"(a0), "r"(a1), "r"(a2), "r"(a3), "r"(b0), "r"(b1));
}
__device__ __forceinline__ void cpa16(uint32_t s, const void* g) {
    asm volatile("cp.async.cg.shared.global [%0], [%1], 16;" :: "r"(s), "l"(g));
}
#define CP_COMMIT() asm volatile("cp.async.commit_group;" ::: "memory")
#define CP_WAIT(n)  asm volatile("cp.async.wait_group %0;" :: "n"(n) : "memory")

#define SW128(off) ((off) ^ (((off) >> 3) & 0x70))
#define SW64B(off) ((off) ^ (((off) >> 3) & 0x30))

// ---------------------------------------------------------------------------
// Pre-pass 1: split fp32 -> fp16 hi/lo
// ---------------------------------------------------------------------------
__global__ void split_kernel(const float* __restrict__ X,
                             __half* __restrict__ H,
                             __half* __restrict__ L, int n4)
{
    int i = blockIdx.x * blockDim.x + threadIdx.x;
    if (i >= n4) return;
    float4 v = reinterpret_cast<const float4*>(X)[i];
    float f[4] = {v.x, v.y, v.z, v.w};
    __half h[4], l[4];
    #pragma unroll
    for (int j = 0; j < 4; j++) f16split(f[j], h[j], l[j]);
    reinterpret_cast<uint2*>(H)[i] = make_uint2(pack2h(h[0], h[1]), pack2h(h[2], h[3]));
    reinterpret_cast<uint2*>(L)[i] = make_uint2(pack2h(l[0], l[1]), pack2h(l[2], l[3]));
}

// ---------------------------------------------------------------------------
// Pre-pass 2: W [K][N] fp32 -> WT [N][K] fp16 (rounded, hi only)
// ---------------------------------------------------------------------------
__global__ void transpose_round_kernel(const float* __restrict__ W,
                                       __half* __restrict__ Th,
                                       int K, int N)
{
    __shared__ float t[32][33];
    int n0 = blockIdx.x * 32, k0 = blockIdx.y * 32;
    int tx = threadIdx.x, ty = threadIdx.y;
    #pragma unroll
    for (int i = 0; i < 32; i += 8)
        t[ty + i][tx] = W[(size_t)(k0 + ty + i) * N + n0 + tx];
    __syncthreads();
    #pragma unroll
    for (int i = 0; i < 32; i += 8)
        Th[(size_t)(n0 + ty + i) * K + k0 + tx] = __float2half_rn(t[tx][ty + i]);
}

// ---------------------------------------------------------------------------
// fp16 2-term mma.sync GEMM: C = (Ah + Al) @ Bh^T + bias.
// A split to ~22 bits (hi/lo fp16); B rounded to fp16. 2 MMAs per pair.
// 3-stage cp.async pipeline, SW64 swizzle, single barrier per chunk.
// Stage (24 KB): AH[128x64B] AL BH.
// mode 0: fp32 out. mode 1: fp16 hi/lo out (lo only for Q cols), Q scaled 0.125.
// ---------------------------------------------------------------------------
__global__ void __launch_bounds__(256, 2)
gemm_mma_kernel(const __half* __restrict__ Ah,
                const __half* __restrict__ Al,
                const __half* __restrict__ Bh,
                const float* __restrict__ bias,
                float* __restrict__ Cf,
                __half* __restrict__ Ch,
                __half* __restrict__ Cl,
                int N, int K, int mode)
{
    extern __shared__ char dsm[];
    constexpr int STAGE = 24576;          // 3 arrays * 8192 B
    const uint32_t sb0 = ssa(dsm);

    const int tid = threadIdx.x;
    const int wid = tid >> 5;
    const int wr = wid & 3;
    const int wc = wid >> 2;
    const int lane = tid & 31;
    const int g = lane >> 2;
    const int t = lane & 3;
    const int lr  = lane & 7;
    const int tlo = (lane >> 3) & 1;
    const int thi = lane >> 4;
    const int blockRow = blockIdx.y * 128;
    const int blockCol = blockIdx.x * 128;
    const int NC = K / 32;                // 32 chunks

    float c[2][8][4];
    #pragma unroll
    for (int mf = 0; mf < 2; mf++)
        #pragma unroll
        for (int nf = 0; nf < 8; nf++)
            #pragma unroll
            for (int i = 0; i < 4; i++) c[mf][nf][i] = 0.f;

    auto load_chunk = [&](int cc) {
        const uint32_t sb = sb0 + (cc % 3) * STAGE;
        const int kt = cc * 32;
        #pragma unroll
        for (int i = 0; i < 2; i++) {
            int id = tid + i * 256;           // 0..511
            int row = id >> 2, u = id & 3;    // 128 rows x 4 x 16B
            uint32_t off = SW64B(row * 64 + u * 16);
            size_t ga = (size_t)(blockRow + row) * K + kt + u * 8;
            size_t gb = (size_t)(blockCol + row) * K + kt + u * 8;
            cpa16(sb + off,         Ah + ga);
            cpa16(sb +  8192 + off, Al + ga);
            cpa16(sb + 16384 + off, Bh + gb);
        }
        CP_COMMIT();
    };

    load_chunk(0);
    load_chunk(1);

    for (int cc = 0; cc < NC; cc++) {
        if (cc + 1 < NC) CP_WAIT(1); else CP_WAIT(0);
        __syncthreads();
        if (cc + 2 < NC) load_chunk(cc + 2);

        const uint32_t sb = sb0 + (cc % 3) * STAGE;
        #pragma unroll
        for (int ks = 0; ks < 2; ks++) {
            unsigned ah[2][4], al_[2][4];
            #pragma unroll
            for (int mf = 0; mf < 2; mf++) {
                int row = wr * 32 + mf * 16 + tlo * 8 + lr;
                uint32_t off = SW64B(row * 64 + ks * 32 + thi * 16);
                ldsm4(ah[mf][0], ah[mf][1], ah[mf][2], ah[mf][3], sb + off);
                ldsm4(al_[mf][0], al_[mf][1], al_[mf][2], al_[mf][3], sb + 8192 + off);
            }
            #pragma unroll
            for (int np = 0; np < 4; np++) {
                int nrow = wc * 64 + np * 16 + thi * 8 + lr;
                uint32_t off = SW64B(nrow * 64 + ks * 32 + tlo * 16);
                unsigned bh[4];
                ldsm4(bh[0], bh[1], bh[2], bh[3], sb + 16384 + off);
                #pragma unroll
                for (int half = 0; half < 2; half++) {
                    int nf = np * 2 + half;
                    unsigned b0h = bh[2 * half], b1h = bh[2 * half + 1];
                    #pragma unroll
                    for (int mf = 0; mf < 2; mf++) {
                        mma16(c[mf][nf], ah[mf][0], ah[mf][1], ah[mf][2], ah[mf][3], b0h, b1h);
                        mma16(c[mf][nf], al_[mf][0], al_[mf][1], al_[mf][2], al_[mf][3], b0h, b1h);
                    }
                }
            }
        }
    }

    // epilogue
    const bool isQ = (mode == 1 && blockCol < DD);
    const float qs = isQ ? 0.125f : 1.0f;
    #pragma unroll
    for (int mf = 0; mf < 2; mf++) {
        int row = blockRow + wr * 32 + mf * 16 + g;
        #pragma unroll
        for (int nf = 0; nf < 8; nf++) {
            int col = blockCol + wc * 64 + nf * 8 + 2 * t;
            float bx = bias[col], by = bias[col + 1];
            float v0 = (c[mf][nf][0] + bx) * qs;
            float v1 = (c[mf][nf][1] + by) * qs;
            float v2 = (c[mf][nf][2] + bx) * qs;
            float v3 = (c[mf][nf][3] + by) * qs;
            if (mode == 0) {
                *reinterpret_cast<float2*>(&Cf[(size_t)row * N + col]) = make_float2(v0, v1);
                *reinterpret_cast<float2*>(&Cf[(size_t)(row + 8) * N + col]) = make_float2(v2, v3);
            } else {
                __half h0, l0, h1, l1;
                f16split(v0, h0, l0); f16split(v1, h1, l1);
                *reinterpret_cast<unsigned*>(&Ch[(size_t)row * N + col]) = pack2h(h0, h1);
                if (isQ)
                    *reinterpret_cast<unsigned*>(&Cl[(size_t)row * N + col]) = pack2h(l0, l1);
                f16split(v2, h0, l0); f16split(v3, h1, l1);
                *reinterpret_cast<unsigned*>(&Ch[(size_t)(row + 8) * N + col]) = pack2h(h0, h1);
                if (isQ)
                    *reinterpret_cast<unsigned*>(&Cl[(size_t)(row + 8) * N + col]) = pack2h(l0, l1);
            }
        }
    }
}

// ---------------------------------------------------------------------------
// Flash attention, fp16 2-term (Q and P split hi/lo; K and V rounded fp16).
// Block = 64 q rows of one (b,h); 128 threads = 4 warps; 32 KB smem, 4 CTAs/SM.
// Split K/V commit groups:
// wait K -> S -> sync -> issue K(kt+1) -> softmax -> wait V -> PV -> issue V(kt+1).
// ---------------------------------------------------------------------------
__global__ void __launch_bounds__(128, 4)
attn_tc_kernel(const __half* __restrict__ qh,
               const __half* __restrict__ ql,
               __half* __restrict__ outH,
               __half* __restrict__ outL)
{
    extern __shared__ char asm_[];
    const uint32_t QHs = ssa(asm_);
    const uint32_t QLs = QHs + 8192;
    const uint32_t KHs = QHs + 16384;
    const uint32_t VHs = QHs + 24576;

    const int b = blockIdx.z;
    const int h = blockIdx.y;
    const int qt = blockIdx.x;
    const int tid = threadIdx.x;
    const int w = tid >> 5;
    const int lane = tid & 31;
    const int g = lane >> 2;
    const int t = lane & 3;
    const int lr  = lane & 7;
    const int tlo = (lane >> 3) & 1;
    const int thi = lane >> 4;
    const int t0 = qt * 64;
    const int NT = TT / 64;

    const size_t rowstride = 3 * DD;
    const size_t base = (size_t)(b * TT) * rowstride + h * HDD;

    auto load_k = [&](int kt) {
        #pragma unroll
        for (int i = 0; i < 4; i++) {
            int id = tid + i * 128;                 // 0..511
            int r = id >> 3, u = id & 7;
            uint32_t so = SW128(r * 128 + u * 16);
            size_t go = base + DD + (size_t)(kt * 64 + r) * rowstride + u * 8;
            cpa16(KHs + so, qh + go);
        }
        CP_COMMIT();
    };
    auto load_v = [&](int kt) {
        #pragma unroll
        for (int i = 0; i < 4; i++) {
            int id = tid + i * 128;
            int r = id >> 3, u = id & 7;
            uint32_t so = SW128(r * 128 + u * 16);
            size_t go = base + 2 * DD + (size_t)(kt * 64 + r) * rowstride + u * 8;
            cpa16(VHs + so, qh + go);
        }
        CP_COMMIT();
    };

    // Q tile load (hi+lo, own commit group), then K0, V0
    {
        #pragma unroll
        for (int i = 0; i < 4; i++) {
            int id = tid + i * 128;
            int r = id >> 3, u = id & 7;
            uint32_t so = SW128(r * 128 + u * 16);
            size_t go = base + (size_t)(t0 + r) * rowstride + u * 8;
            cpa16(QHs + so, qh + go);
            cpa16(QLs + so, ql + go);
        }
        CP_COMMIT();
    }
    load_k(0);
    load_v(0);

    float o[8][4];
    #pragma unroll
    for (int nf = 0; nf < 8; nf++)
        #pragma unroll
        for (int i = 0; i < 4; i++) o[nf][i] = 0.f;
    float m[2] = {-1e30f, -1e30f};
    float l2s[2] = {0.f, 0.f};

    for (int kt = 0; kt < NT; kt++) {
        // wait for K(kt) (V(kt) may still be in flight)
        CP_WAIT(1);
        __syncthreads();

        // ---- S = Q @ K^T ----
        float sc[8][4];
        #pragma unroll
        for (int nf = 0; nf < 8; nf++)
            #pragma unroll
            for (int i = 0; i < 4; i++) sc[nf][i] = 0.f;

        #pragma unroll
        for (int ks = 0; ks < 4; ks++) {
            unsigned qfh[4], qfl[4];
            {
                int row = 16 * w + tlo * 8 + lr;
                uint32_t so = SW128(row * 128 + ks * 32 + thi * 16);
                ldsm4(qfh[0], qfh[1], qfh[2], qfh[3], QHs + so);
                ldsm4(qfl[0], qfl[1], qfl[2], qfl[3], QLs + so);
            }
            #pragma unroll
            for (int np = 0; np < 4; np++) {
                int row = np * 16 + thi * 8 + lr;
                uint32_t so = SW128(row * 128 + ks * 32 + tlo * 16);
                unsigned kh[4];
                ldsm4(kh[0], kh[1], kh[2], kh[3], KHs + so);
                #pragma unroll
                for (int half = 0; half < 2; half++) {
                    int nf = np * 2 + half;
                    unsigned b0h = kh[2 * half], b1h = kh[2 * half + 1];
                    mma16(sc[nf], qfh[0], qfh[1], qfh[2], qfh[3], b0h, b1h);
                    mma16(sc[nf], qfl[0], qfl[1], qfl[2], qfl[3], b0h, b1h);
                }
            }
        }

        __syncthreads();                 // all warps done reading K buffer
        if (kt + 1 < NT) load_k(kt + 1); // K(kt+1) hides behind softmax + PV

        // ---- online softmax (registers only) ----
        #pragma unroll
        for (int r = 0; r < 2; r++) {
            float mx = -1e30f;
            #pragma unroll
            for (int nf = 0; nf < 8; nf++)
                mx = fmaxf(mx, fmaxf(sc[nf][2 * r], sc[nf][2 * r + 1]));
            mx = fmaxf(mx, __shfl_xor_sync(0xffffffffu, mx, 1));
            mx = fmaxf(mx, __shfl_xor_sync(0xffffffffu, mx, 2));
            float mn = fmaxf(m[r], mx);
            float alpha = __expf(m[r] - mn);
            m[r] = mn;
            float sum = 0.f;
            #pragma unroll
            for (int nf = 0; nf < 8; nf++) {
                float p0 = __expf(sc[nf][2 * r] - mn);
                float p1 = __expf(sc[nf][2 * r + 1] - mn);
                sc[nf][2 * r] = p0;
                sc[nf][2 * r + 1] = p1;
                sum += p0 + p1;
            }
            sum += __shfl_xor_sync(0xffffffffu, sum, 1);
            sum += __shfl_xor_sync(0xffffffffu, sum, 2);
            l2s[r] = l2s[r] * alpha + sum;
            #pragma unroll
            for (int nf = 0; nf < 8; nf++) {
                o[nf][2 * r] *= alpha;
                o[nf][2 * r + 1] *= alpha;
            }
        }

        // wait for V(kt); one group (K(kt+1)) may remain outstanding
        if (kt + 1 < NT) CP_WAIT(1); else CP_WAIT(0);
        __syncthreads();

        // ---- O += P @ V  (P split hi/lo fp16, V rounded) ----
        #pragma unroll
        for (int ks2 = 0; ks2 < 4; ks2++) {
            unsigned pa_h[4], pa_l[4];
            #pragma unroll
            for (int half = 0; half < 2; half++) {
                const float* s4 = sc[2 * ks2 + half];
                __half h0, l0, h1, l1, h2, l2, h3, l3;
                f16split(s4[0], h0, l0);
                f16split(s4[1], h1, l1);
                f16split(s4[2], h2, l2);
                f16split(s4[3], h3, l3);
                pa_h[2 * half]     = pack2h(h0, h1);
                pa_h[2 * half + 1] = pack2h(h2, h3);
                pa_l[2 * half]     = pack2h(l0, l1);
                pa_l[2 * half + 1] = pack2h(l2, l3);
            }
            #pragma unroll
            for (int np = 0; np < 4; np++) {
                int vr = ks2 * 16 + tlo * 8 + lr;
                uint32_t so = SW128(vr * 128 + np * 32 + thi * 16);
                unsigned vh[4];
                ldsm4t(vh[0], vh[1], vh[2], vh[3], VHs + so);
                #pragma unroll
                for (int half = 0; half < 2; half++) {
                    int nfo = np * 2 + half;
                    unsigned b0h = vh[2 * half], b1h = vh[2 * half + 1];
                    mma16(o[nfo], pa_h[0], pa_h[1], pa_h[2], pa_h[3], b0h, b1h);
                    mma16(o[nfo], pa_l[0], pa_l[1], pa_l[2], pa_l[3], b0h, b1h);
                }
            }
        }

        __syncthreads();                 // all warps done reading V buffer
        if (kt + 1 < NT) load_v(kt + 1); // V(kt+1) hides behind next S + softmax
    }

    // normalize + write fp16 hi/lo
    #pragma unroll
    for (int r = 0; r < 2; r++) {
        float inv = 1.f / l2s[r];
        int row = t0 + 16 * w + g + 8 * r;
        #pragma unroll
        for (int nf = 0; nf < 8; nf++) {
            int col = h * HDD + nf * 8 + 2 * t;
            float v0 = o[nf][2 * r] * inv;
            float v1 = o[nf][2 * r + 1] * inv;
            __half h0, l0, h1, l1;
            f16split(v0, h0, l0);
            f16split(v1, h1, l1);
            size_t idx = (size_t)(b * TT + row) * DD + col;
            *reinterpret_cast<unsigned*>(&outH[idx]) = pack2h(h0, h1);
            *reinterpret_cast<unsigned*>(&outL[idx]) = pack2h(l0, l1);
        }
    }
}

// ---------------------------------------------------------------------------
extern "C" void kernel_launch(void* const* d_in, const int* in_sizes, int n_in,
                              void* d_out, int out_size)
{
    const float* x     = (const float*)d_in[0];
    const float* w_qkv = (const float*)d_in[1];
    const float* b_qkv = (const float*)d_in[2];
    const float* w_out = (const float*)d_in[3];
    const float* b_out = (const float*)d_in[4];
    float* out = (float*)d_out;

    __half *xh, *xl, *wqh, *woh, *qkvh, *qkvl, *ah, *al;
    cudaGetSymbolAddress((void**)&xh,   g_xh);
    cudaGetSymbolAddress((void**)&xl,   g_xl);
    cudaGetSymbolAddress((void**)&wqh,  g_wqkvT_h);
    cudaGetSymbolAddress((void**)&woh,  g_woutT_h);
    cudaGetSymbolAddress((void**)&qkvh, g_qkvH);
    cudaGetSymbolAddress((void**)&qkvl, g_qkvL);
    cudaGetSymbolAddress((void**)&ah,   g_attnH);
    cudaGetSymbolAddress((void**)&al,   g_attnL);

    const int GEMM_SMEM = 3 * 24576;   // 72 KB, 3-stage
    cudaFuncSetAttribute(gemm_mma_kernel,
                         cudaFuncAttributeMaxDynamicSharedMemorySize, GEMM_SMEM);
    const int ATTN_SMEM = 4 * 8192;    // 32 KB
    cudaFuncSetAttribute(attn_tc_kernel,
                         cudaFuncAttributeMaxDynamicSharedMemorySize, ATTN_SMEM);

    // Pre-pass: split X (hi/lo); transpose+round weights (hi only)
    {
        int n4 = BB * TT * DD / 4;
        split_kernel<<<(n4 + 255) / 256, 256>>>(x, xh, xl, n4);
        dim3 bt(32, 8);
        transpose_round_kernel<<<dim3(3 * DD / 32, DD / 32), bt>>>(w_qkv, wqh, DD, 3 * DD);
        transpose_round_kernel<<<dim3(DD / 32, DD / 32), bt>>>(w_out, woh, DD, DD);
    }

    // 1) QKV projection -> fp16 hi/lo (Q pre-scaled by 0.125; lo only for Q)
    gemm_mma_kernel<<<dim3(3 * DD / 128, BB * TT / 128), 256, GEMM_SMEM>>>(
        xh, xl, wqh, b_qkv, nullptr, qkvh, qkvl, 3 * DD, DD, 1);

    // 2) Attention -> fp16 hi/lo (64-row Q tiles, proven config)
    attn_tc_kernel<<<dim3(TT / 64, HH, BB), 128, ATTN_SMEM>>>(qkvh, qkvl, ah, al);

    // 3) Output projection -> fp32 d_out
    gemm_mma_kernel<<<dim3(DD / 128, BB * TT / 128), 256, GEMM_SMEM>>>(
        ah, al, woh, b_out, out, nullptr, nullptr, DD, DD, 0);
}